// round 1
// baseline (speedup 1.0000x reference)
#include <cuda_runtime.h>
#include <cstdint>

// Fused int4 group-dequant + SGEMM baseline.
// y[m][n] = sum_k x[m][k] * (scale[n][k/128] * (q(n,k) - zp[n][k/128])) + bias[n]
// q(n,k) = (qweight[n][k/8] >> (4*(k%8))) & 0xF
//
// Tiling: 128x128 output tile per CTA, BK=16, 256 threads, 8x8 register tile
// per thread. Weights dequantized on the fly into SMEM (they're only 8 MB
// packed, L2-resident). Register prefetch double-buffers global loads across
// the compute phase.

namespace {

constexpr int BM = 128;
constexpr int BN = 128;
constexpr int BK = 16;
constexpr int TM = 8;
constexpr int TN = 8;
constexpr int THREADS = 256;

__global__ __launch_bounds__(THREADS)
void dq_gemm_kernel(const float* __restrict__ X,    // [M, K]
                    const int*   __restrict__ QW,   // [N, K/8]
                    const float* __restrict__ SC,   // [N, K/128]
                    const float* __restrict__ ZP,   // [N, K/128]
                    const float* __restrict__ BIAS, // [N]
                    float* __restrict__ Y,          // [M, N]
                    int M, int N, int K)
{
    __shared__ float As[BK][BM];   // A stored k-major (transposed)
    __shared__ float Bs[BK][BN];   // dequantized weights, k-major

    const int tid = threadIdx.x;
    const int bm = blockIdx.y * BM;
    const int bn = blockIdx.x * BN;
    const int tx = tid & 15;    // n direction (16 threads)
    const int ty = tid >> 4;    // m direction (16 threads)

    const int kWords  = K >> 3; // int32 words per weight row
    const int nGroups = K >> 7; // quant groups per row (group_size = 128)

    // --- A tile load mapping: 128 rows x 16 cols = 512 float4, 2 per thread
    const int a_row0 = (tid)           >> 2;
    const int a_c40  = ((tid)      & 3) << 2;
    const int a_row1 = (tid + 256)     >> 2;
    const int a_c41  = ((tid + 256) & 3) << 2;
    const float* a_ptr0 = X + (size_t)(bm + a_row0) * K + a_c40;
    const float* a_ptr1 = X + (size_t)(bm + a_row1) * K + a_c41;

    // --- W tile load mapping: 128 rows x 2 int32 words, 1 word per thread
    const int wrow = tid >> 1;
    const int wcol = tid & 1;
    const int*   qw_ptr = QW + (size_t)(bn + wrow) * kWords + wcol;
    const float* sc_row = SC + (size_t)(bn + wrow) * nGroups;
    const float* zp_row = ZP + (size_t)(bn + wrow) * nGroups;

    float acc[TM][TN];
    #pragma unroll
    for (int i = 0; i < TM; i++)
        #pragma unroll
        for (int j = 0; j < TN; j++) acc[i][j] = 0.f;

    // Prefetch registers for the NEXT tile
    float4 pa0, pa1;
    unsigned pw;
    float ps, pz;

    // ---- load tile 0 directly into smem ----
    {
        float4 v0 = *reinterpret_cast<const float4*>(a_ptr0);
        float4 v1 = *reinterpret_cast<const float4*>(a_ptr1);
        As[a_c40 + 0][a_row0] = v0.x;
        As[a_c40 + 1][a_row0] = v0.y;
        As[a_c40 + 2][a_row0] = v0.z;
        As[a_c40 + 3][a_row0] = v0.w;
        As[a_c41 + 0][a_row1] = v1.x;
        As[a_c41 + 1][a_row1] = v1.y;
        As[a_c41 + 2][a_row1] = v1.z;
        As[a_c41 + 3][a_row1] = v1.w;

        float s = sc_row[0];
        float z = zp_row[0];
        unsigned word = (unsigned)qw_ptr[0];
        float szneg = -s * z;
        #pragma unroll
        for (int i = 0; i < 8; i++) {
            float q = (float)((word >> (4 * i)) & 0xFu);
            Bs[wcol * 8 + i][wrow] = fmaf(s, q, szneg);
        }
    }

    const int nTiles = K / BK;
    for (int t = 0; t < nTiles; t++) {
        __syncthreads();

        // prefetch next tile's globals while computing on current smem
        const bool has_next = (t + 1 < nTiles);
        if (has_next) {
            int k0n = (t + 1) * BK;
            pa0 = *reinterpret_cast<const float4*>(a_ptr0 + k0n);
            pa1 = *reinterpret_cast<const float4*>(a_ptr1 + k0n);
            int g = k0n >> 7;
            ps = sc_row[g];
            pz = zp_row[g];
            pw = (unsigned)qw_ptr[k0n >> 3];
        }

        // ---- compute on current tile ----
        #pragma unroll
        for (int kk = 0; kk < BK; kk++) {
            float a[TM], b[TN];
            #pragma unroll
            for (int i = 0; i < TM; i += 4)
                *reinterpret_cast<float4*>(&a[i]) =
                    *reinterpret_cast<const float4*>(&As[kk][ty * TM + i]);
            #pragma unroll
            for (int j = 0; j < TN; j += 4)
                *reinterpret_cast<float4*>(&b[j]) =
                    *reinterpret_cast<const float4*>(&Bs[kk][tx * TN + j]);
            #pragma unroll
            for (int i = 0; i < TM; i++)
                #pragma unroll
                for (int j = 0; j < TN; j++)
                    acc[i][j] = fmaf(a[i], b[j], acc[i][j]);
        }

        __syncthreads();

        // ---- commit prefetched tile into smem ----
        if (has_next) {
            As[a_c40 + 0][a_row0] = pa0.x;
            As[a_c40 + 1][a_row0] = pa0.y;
            As[a_c40 + 2][a_row0] = pa0.z;
            As[a_c40 + 3][a_row0] = pa0.w;
            As[a_c41 + 0][a_row1] = pa1.x;
            As[a_c41 + 1][a_row1] = pa1.y;
            As[a_c41 + 2][a_row1] = pa1.z;
            As[a_c41 + 3][a_row1] = pa1.w;
            float szneg = -ps * pz;
            #pragma unroll
            for (int i = 0; i < 8; i++) {
                float q = (float)((pw >> (4 * i)) & 0xFu);
                Bs[wcol * 8 + i][wrow] = fmaf(ps, q, szneg);
            }
        }
    }

    // ---- epilogue: add bias, store ----
    float bvals[TN];
    #pragma unroll
    for (int j = 0; j < TN; j++) bvals[j] = BIAS[bn + tx * TN + j];

    #pragma unroll
    for (int i = 0; i < TM; i++) {
        int m = bm + ty * TM + i;
        float* yrow = Y + (size_t)m * N + bn + tx * TN;
        #pragma unroll
        for (int j = 0; j < TN; j += 4) {
            float4 v;
            v.x = acc[i][j + 0] + bvals[j + 0];
            v.y = acc[i][j + 1] + bvals[j + 1];
            v.z = acc[i][j + 2] + bvals[j + 2];
            v.w = acc[i][j + 3] + bvals[j + 3];
            *reinterpret_cast<float4*>(yrow + j) = v;
        }
    }
}

} // namespace

extern "C" void kernel_launch(void* const* d_in, const int* in_sizes, int n_in,
                              void* d_out, int out_size)
{
    const float* x    = (const float*)d_in[0];
    const int*   qw   = (const int*)d_in[1];
    const float* sc   = (const float*)d_in[2];
    const float* zp   = (const float*)d_in[3];
    const float* bias = (const float*)d_in[4];
    float* y = (float*)d_out;

    const int N = in_sizes[4];                         // bias length
    const long long K = ((long long)in_sizes[1] * 8) / N;  // qweight = N*K/8
    const long long M = (long long)in_sizes[0] / K;        // x = M*K

    dim3 grid((unsigned)(N / BN), (unsigned)(M / BM));
    dq_gemm_kernel<<<grid, THREADS>>>(x, qw, sc, zp, bias, y,
                                      (int)M, N, (int)K);
}

// round 3
// speedup vs baseline: 2.6628x; 2.6628x over previous
#include <cuda_runtime.h>
#include <cuda_bf16.h>
#include <cstdint>

// Fused int4 group-dequant + GEMM via legacy mma.sync bf16 (base sm_103 ISA —
// the harness PTX target lacks the 'a' suffix, so tcgen05 is unavailable).
// Split precision: x = xh + xl, w = wh + wl (bf16 each);
// y ~= xh*wh + xh*wl + xl*wh (fp32 accum), error ~2^-17.

namespace {

constexpr int MMAX = 8192, NMAX = 4096, KMAX = 4096;

// device-global scratch (allocation-free per harness rules)
__device__ __nv_bfloat16 g_Xh[(size_t)MMAX * KMAX];
__device__ __nv_bfloat16 g_Xl[(size_t)MMAX * KMAX];
__device__ __nv_bfloat16 g_Wh[(size_t)NMAX * KMAX];
__device__ __nv_bfloat16 g_Wl[(size_t)NMAX * KMAX];

constexpr int BM = 128, BN = 128, BK = 64;
constexpr int THREADS = 256;
constexpr int ROWB  = 144;              // 64 bf16 = 128B + 16B pad (16B-aligned, bank-staggered)
constexpr int TILEB = BM * ROWB;        // 18432 B per [128 x 64] bf16 tile
constexpr int AH_OFF = 0;
constexpr int AL_OFF = TILEB;
constexpr int WH_OFF = 2 * TILEB;
constexpr int WL_OFF = 3 * TILEB;
constexpr int STAGE  = 4 * TILEB;       // 73728
constexpr int SMEM_TOTAL = 2 * STAGE;   // 147456

__device__ __forceinline__ uint32_t smem_u32(const void* p) {
    uint32_t a;
    asm("{ .reg .u64 t; cvta.to.shared.u64 t, %1; cvt.u32.u64 %0, t; }"
        : "=r"(a) : "l"(p));
    return a;
}
__device__ __forceinline__ void cp16(uint32_t dst, const void* src) {
    asm volatile("cp.async.cg.shared.global [%0], [%1], 16;"
                 :: "r"(dst), "l"(src) : "memory");
}
#define CP_COMMIT() asm volatile("cp.async.commit_group;" ::: "memory")
#define CP_WAIT_1() asm volatile("cp.async.wait_group 1;" ::: "memory")
#define CP_WAIT_0() asm volatile("cp.async.wait_group 0;" ::: "memory")

__device__ __forceinline__ void ldsm_x4(uint32_t* r, uint32_t addr) {
    asm volatile("ldmatrix.sync.aligned.m8n8.x4.shared.b16 {%0,%1,%2,%3}, [%4];"
                 : "=r"(r[0]), "=r"(r[1]), "=r"(r[2]), "=r"(r[3]) : "r"(addr));
}
__device__ __forceinline__ uint32_t lds32(uint32_t addr) {
    uint32_t v;
    asm volatile("ld.shared.b32 %0, [%1];" : "=r"(v) : "r"(addr));
    return v;
}
__device__ __forceinline__ void mma_bf16(float* c, const uint32_t* a,
                                         const uint32_t* b) {
    asm volatile(
        "mma.sync.aligned.m16n8k16.row.col.f32.bf16.bf16.f32 "
        "{%0,%1,%2,%3}, {%4,%5,%6,%7}, {%8,%9}, {%0,%1,%2,%3};"
        : "+f"(c[0]), "+f"(c[1]), "+f"(c[2]), "+f"(c[3])
        : "r"(a[0]), "r"(a[1]), "r"(a[2]), "r"(a[3]), "r"(b[0]), "r"(b[1]));
}

// ---- pre-pass: split x into bf16 hi/lo ----
__global__ __launch_bounds__(256)
void convert_x_kernel(const float* __restrict__ X, long total4) {
    long i = (long)blockIdx.x * blockDim.x + threadIdx.x;
    if (i >= total4) return;
    float4 v = reinterpret_cast<const float4*>(X)[i];
    __nv_bfloat16 h0 = __float2bfloat16(v.x);
    __nv_bfloat16 h1 = __float2bfloat16(v.y);
    __nv_bfloat16 h2 = __float2bfloat16(v.z);
    __nv_bfloat16 h3 = __float2bfloat16(v.w);
    __nv_bfloat16 l0 = __float2bfloat16(v.x - __bfloat162float(h0));
    __nv_bfloat16 l1 = __float2bfloat16(v.y - __bfloat162float(h1));
    __nv_bfloat16 l2 = __float2bfloat16(v.z - __bfloat162float(h2));
    __nv_bfloat16 l3 = __float2bfloat16(v.w - __bfloat162float(h3));
    __nv_bfloat162* H = reinterpret_cast<__nv_bfloat162*>(g_Xh);
    __nv_bfloat162* L = reinterpret_cast<__nv_bfloat162*>(g_Xl);
    H[2 * i]     = __halves2bfloat162(h0, h1);
    H[2 * i + 1] = __halves2bfloat162(h2, h3);
    L[2 * i]     = __halves2bfloat162(l0, l1);
    L[2 * i + 1] = __halves2bfloat162(l2, l3);
}

// ---- pre-pass: dequant W (int4, group scale/zp) into bf16 hi/lo ----
__global__ __launch_bounds__(256)
void convert_w_kernel(const int* __restrict__ QW, const float* __restrict__ SC,
                      const float* __restrict__ ZP, int wordsPerRow, int nGroups,
                      long totalWords) {
    long i = (long)blockIdx.x * blockDim.x + threadIdx.x;
    if (i >= totalWords) return;
    int n = (int)(i / wordsPerRow);
    int w = (int)(i % wordsPerRow);
    int g = (w * 8) >> 7;  // group_size 128 = 16 words
    float s = SC[(size_t)n * nGroups + g];
    float z = ZP[(size_t)n * nGroups + g];
    float szn = -s * z;
    unsigned q = (unsigned)QW[i];
    __nv_bfloat162 hh[4], ll[4];
#pragma unroll
    for (int j = 0; j < 4; j++) {
        float f0 = fmaf(s, (float)((q >> (8 * j)) & 0xFu), szn);
        float f1 = fmaf(s, (float)((q >> (8 * j + 4)) & 0xFu), szn);
        __nv_bfloat16 h0 = __float2bfloat16(f0);
        __nv_bfloat16 h1 = __float2bfloat16(f1);
        __nv_bfloat16 l0 = __float2bfloat16(f0 - __bfloat162float(h0));
        __nv_bfloat16 l1 = __float2bfloat16(f1 - __bfloat162float(h1));
        hh[j] = __halves2bfloat162(h0, h1);
        ll[j] = __halves2bfloat162(l0, l1);
    }
    reinterpret_cast<uint4*>(g_Wh)[i] = *reinterpret_cast<uint4*>(hh);
    reinterpret_cast<uint4*>(g_Wl)[i] = *reinterpret_cast<uint4*>(ll);
}

// ---- main GEMM: 128x128 CTA, BK=64, 8 warps (2x4), warp tile 64x32 ----
__global__ __launch_bounds__(THREADS, 1)
void gemm_kernel(const float* __restrict__ BIAS, float* __restrict__ Y,
                 int M, int N, int K) {
    extern __shared__ char smem[];
    const uint32_t su = smem_u32(smem);
    const int tid  = threadIdx.x;
    const int lane = tid & 31;
    const int wid  = tid >> 5;
    const int bm = blockIdx.y * BM;
    const int bn = blockIdx.x * BN;
    const int mw = (wid >> 2) * 64;   // warp m offset (2 warps in m)
    const int nw = (wid & 3) * 32;    // warp n offset (4 warps in n)

    // per-ktile stage loader: 16 x 16B chunks per thread (4 arrays x 4)
    auto load_stage = [&](int s, int t) {
        const uint32_t sb = su + s * STAGE;
        const size_t k0 = (size_t)t * BK;
#pragma unroll
        for (int j = 0; j < 4; j++) {
            int idx = tid + j * THREADS;       // 0..1023
            int r = idx >> 3;                  // row 0..127
            int c = idx & 7;                   // 16B chunk 0..7
            uint32_t doff = (uint32_t)(r * ROWB + c * 16);
            const char* xh = (const char*)(g_Xh + (size_t)(bm + r) * K + k0) + c * 16;
            const char* xl = (const char*)(g_Xl + (size_t)(bm + r) * K + k0) + c * 16;
            const char* wh = (const char*)(g_Wh + (size_t)(bn + r) * K + k0) + c * 16;
            const char* wl = (const char*)(g_Wl + (size_t)(bn + r) * K + k0) + c * 16;
            cp16(sb + AH_OFF + doff, xh);
            cp16(sb + AL_OFF + doff, xl);
            cp16(sb + WH_OFF + doff, wh);
            cp16(sb + WL_OFF + doff, wl);
        }
        CP_COMMIT();
    };

    float acc[4][4][4];
#pragma unroll
    for (int i = 0; i < 4; i++)
#pragma unroll
        for (int j = 0; j < 4; j++)
#pragma unroll
            for (int c = 0; c < 4; c++) acc[i][j][c] = 0.f;

    const int T = K / BK;   // 64
    load_stage(0, 0);
    load_stage(1, 1);

    // precomputed lane addressing pieces
    const uint32_t a_r  = (uint32_t)((lane & 7) + ((lane >> 3) & 1) * 8);  // row within m16
    const uint32_t a_cb = (uint32_t)(((lane >> 4) & 1) * 16);              // k-half byte
    const uint32_t b_g  = (uint32_t)(lane >> 2);
    const uint32_t b_i4 = (uint32_t)((lane & 3) * 4);

    for (int t = 0; t < T; t++) {
        CP_WAIT_1();
        __syncthreads();
        const uint32_t sb = su + (t & 1) * STAGE;

#pragma unroll
        for (int kk = 0; kk < BK / 16; kk++) {
            const uint32_t kb = (uint32_t)(kk * 32);

            uint32_t ah[4][4], al[4][4];
#pragma unroll
            for (int ms = 0; ms < 4; ms++) {
                uint32_t r = (uint32_t)(mw + ms * 16) + a_r;
                uint32_t ad = sb + AH_OFF + r * ROWB + kb + a_cb;
                ldsm_x4(ah[ms], ad);
                ldsm_x4(al[ms], ad + (AL_OFF - AH_OFF));
            }
            uint32_t bh[4][2], bl[4][2];
#pragma unroll
            for (int ns = 0; ns < 4; ns++) {
                uint32_t nr = (uint32_t)(nw + ns * 8) + b_g;
                uint32_t bo = sb + WH_OFF + nr * ROWB + kb + b_i4;
                bh[ns][0] = lds32(bo);
                bh[ns][1] = lds32(bo + 16);
                bl[ns][0] = lds32(bo + (WL_OFF - WH_OFF));
                bl[ns][1] = lds32(bo + (WL_OFF - WH_OFF) + 16);
            }
#pragma unroll
            for (int ms = 0; ms < 4; ms++)
#pragma unroll
                for (int ns = 0; ns < 4; ns++) {
                    mma_bf16(acc[ms][ns], ah[ms], bh[ns]);   // xh*wh
                    mma_bf16(acc[ms][ns], ah[ms], bl[ns]);   // xh*wl
                    mma_bf16(acc[ms][ns], al[ms], bh[ns]);   // xl*wh
                }
        }

        __syncthreads();
        if (t + 2 < T) load_stage(t & 1, t + 2);
    }

    // epilogue: fused bias, float2 stores
#pragma unroll
    for (int ns = 0; ns < 4; ns++) {
        const int n0 = bn + nw + ns * 8 + 2 * (lane & 3);
        const float bv0 = BIAS[n0];
        const float bv1 = BIAS[n0 + 1];
#pragma unroll
        for (int ms = 0; ms < 4; ms++) {
            const int m0 = bm + mw + ms * 16 + (lane >> 2);
            float2 v;
            v.x = acc[ms][ns][0] + bv0;
            v.y = acc[ms][ns][1] + bv1;
            *reinterpret_cast<float2*>(Y + (size_t)m0 * N + n0) = v;
            v.x = acc[ms][ns][2] + bv0;
            v.y = acc[ms][ns][3] + bv1;
            *reinterpret_cast<float2*>(Y + (size_t)(m0 + 8) * N + n0) = v;
        }
    }
}

}  // namespace

extern "C" void kernel_launch(void* const* d_in, const int* in_sizes, int n_in,
                              void* d_out, int out_size) {
    const float* x    = (const float*)d_in[0];
    const int*   qw   = (const int*)d_in[1];
    const float* sc   = (const float*)d_in[2];
    const float* zp   = (const float*)d_in[3];
    const float* bias = (const float*)d_in[4];
    float* y = (float*)d_out;

    const int N = in_sizes[4];
    const long long K = ((long long)in_sizes[1] * 8) / N;
    const long long M = (long long)in_sizes[0] / K;

    static bool attr_done = false;
    if (!attr_done) {
        cudaFuncSetAttribute(gemm_kernel,
                             cudaFuncAttributeMaxDynamicSharedMemorySize,
                             SMEM_TOTAL);
        attr_done = true;
    }

    {   // split x
        long total4 = (long)M * K / 4;
        int blocks = (int)((total4 + 255) / 256);
        convert_x_kernel<<<blocks, 256>>>(x, total4);
    }
    {   // dequant + split W
        int wordsPerRow = (int)(K / 8);
        int nGroups = (int)(K / 128);
        long totalWords = (long)N * wordsPerRow;
        int blocks = (int)((totalWords + 255) / 256);
        convert_w_kernel<<<blocks, 256>>>(qw, sc, zp, wordsPerRow, nGroups, totalWords);
    }
    {
        dim3 grid((unsigned)(N / BN), (unsigned)(M / BM));
        gemm_kernel<<<grid, THREADS, SMEM_TOTAL>>>(bias, y, (int)M, N, (int)K);
    }
}

// round 4
// speedup vs baseline: 7.1496x; 2.6850x over previous
#include <cuda_runtime.h>
#include <cuda_fp16.h>
#include <cstdint>

// Fused int4 group-dequant + GEMM via single-product fp16 mma.sync.
// fp16 (11-bit mantissa) element error ~2^-11 with random sign cancels over
// K=4096 -> norm rel_err ~3e-4, well under the 1e-3 gate.
// Pre-passes: x -> fp16, dequant(W) -> fp16. Main: 128x256 tile, BK=64,
// 8 warps (warp tile 64x64), 3-stage cp.async pipeline, ldmatrix A and B.

namespace {

constexpr int MMAX = 8192, NMAX = 4096, KMAX = 4096;

__device__ __half g_X[(size_t)MMAX * KMAX];
__device__ __half g_W[(size_t)NMAX * KMAX];

constexpr int BM = 128, BN = 256, BK = 64;
constexpr int THREADS = 256;
constexpr int ROWB = 144;                 // 64 fp16 = 128B + 16B pad
constexpr int A_OFF = 0;
constexpr int B_OFF = BM * ROWB;          // 18432
constexpr int STAGE = B_OFF + BN * ROWB;  // 55296
constexpr int NSTAGES = 3;
constexpr int SMEM_TOTAL = NSTAGES * STAGE;  // 165888

__device__ __forceinline__ uint32_t smem_u32(const void* p) {
    uint32_t a;
    asm("{ .reg .u64 t; cvta.to.shared.u64 t, %1; cvt.u32.u64 %0, t; }"
        : "=r"(a) : "l"(p));
    return a;
}
__device__ __forceinline__ void cp16(uint32_t dst, const void* src) {
    asm volatile("cp.async.cg.shared.global [%0], [%1], 16;"
                 :: "r"(dst), "l"(src) : "memory");
}
#define CP_COMMIT() asm volatile("cp.async.commit_group;" ::: "memory")
#define CP_WAIT(n)  asm volatile("cp.async.wait_group %0;" :: "n"(n) : "memory")

__device__ __forceinline__ void ldsm_x4(uint32_t* r, uint32_t addr) {
    asm volatile("ldmatrix.sync.aligned.m8n8.x4.shared.b16 {%0,%1,%2,%3}, [%4];"
                 : "=r"(r[0]), "=r"(r[1]), "=r"(r[2]), "=r"(r[3]) : "r"(addr));
}
__device__ __forceinline__ void mma_fp16(float* c, const uint32_t* a,
                                         const uint32_t* b) {
    asm volatile(
        "mma.sync.aligned.m16n8k16.row.col.f32.f16.f16.f32 "
        "{%0,%1,%2,%3}, {%4,%5,%6,%7}, {%8,%9}, {%0,%1,%2,%3};"
        : "+f"(c[0]), "+f"(c[1]), "+f"(c[2]), "+f"(c[3])
        : "r"(a[0]), "r"(a[1]), "r"(a[2]), "r"(a[3]), "r"(b[0]), "r"(b[1]));
}

// ---- pre-pass: x -> fp16 ----
__global__ __launch_bounds__(256)
void convert_x_kernel(const float* __restrict__ X, long total4) {
    long i = (long)blockIdx.x * blockDim.x + threadIdx.x;
    if (i >= total4) return;
    float4 v = reinterpret_cast<const float4*>(X)[i];
    __half2* H = reinterpret_cast<__half2*>(g_X);
    H[2 * i]     = __floats2half2_rn(v.x, v.y);
    H[2 * i + 1] = __floats2half2_rn(v.z, v.w);
}

// ---- pre-pass: dequant W (int4, group scale/zp) -> fp16 ----
__global__ __launch_bounds__(256)
void convert_w_kernel(const int* __restrict__ QW, const float* __restrict__ SC,
                      const float* __restrict__ ZP, int wordsPerRow, int nGroups,
                      long totalWords) {
    long i = (long)blockIdx.x * blockDim.x + threadIdx.x;
    if (i >= totalWords) return;
    int n = (int)(i / wordsPerRow);
    int w = (int)(i % wordsPerRow);
    int g = (w * 8) >> 7;  // group_size 128 = 16 int32 words
    float s = SC[(size_t)n * nGroups + g];
    float z = ZP[(size_t)n * nGroups + g];
    float szn = -s * z;
    unsigned q = (unsigned)QW[i];
    __half2 h[4];
#pragma unroll
    for (int j = 0; j < 4; j++) {
        float f0 = fmaf(s, (float)((q >> (8 * j)) & 0xFu), szn);
        float f1 = fmaf(s, (float)((q >> (8 * j + 4)) & 0xFu), szn);
        h[j] = __floats2half2_rn(f0, f1);
    }
    reinterpret_cast<uint2*>(g_W)[2 * i]     = *reinterpret_cast<uint2*>(&h[0]);
    reinterpret_cast<uint2*>(g_W)[2 * i + 1] = *reinterpret_cast<uint2*>(&h[2]);
}

// ---- main GEMM: 128x256 CTA, BK=64, 8 warps (2x4), warp tile 64x64 ----
__global__ __launch_bounds__(THREADS, 1)
void gemm_kernel(const float* __restrict__ BIAS, float* __restrict__ Y,
                 int M, int N, int K) {
    extern __shared__ char smem[];
    const uint32_t su = smem_u32(smem);
    const int tid  = threadIdx.x;
    const int lane = tid & 31;
    const int wid  = tid >> 5;
    const int bm = blockIdx.y * BM;
    const int bn = blockIdx.x * BN;
    const int mw = (wid >> 2) * 64;   // 2 warps along m
    const int nw = (wid & 3) * 64;    // 4 warps along n

    auto load_stage = [&](int s, int t) {
        const uint32_t sb = su + s * STAGE;
        const size_t k0 = (size_t)t * BK;
#pragma unroll
        for (int j = 0; j < 4; j++) {  // A: 128 rows x 8 x 16B
            int idx = tid + j * THREADS;
            int r = idx >> 3, c = idx & 7;
            cp16(sb + A_OFF + (uint32_t)(r * ROWB + c * 16),
                 (const char*)(g_X + (size_t)(bm + r) * K + k0) + c * 16);
        }
#pragma unroll
        for (int j = 0; j < 8; j++) {  // B: 256 rows x 8 x 16B
            int idx = tid + j * THREADS;
            int r = idx >> 3, c = idx & 7;
            cp16(sb + B_OFF + (uint32_t)(r * ROWB + c * 16),
                 (const char*)(g_W + (size_t)(bn + r) * K + k0) + c * 16);
        }
        CP_COMMIT();
    };

    float acc[4][8][4];
#pragma unroll
    for (int i = 0; i < 4; i++)
#pragma unroll
        for (int j = 0; j < 8; j++)
#pragma unroll
            for (int c = 0; c < 4; c++) acc[i][j][c] = 0.f;

    const int T = K / BK;  // 64
    load_stage(0, 0);
    load_stage(1, 1);
    load_stage(2, 2);

    // ldmatrix lane addressing
    // A x4 blocks in reg order: (m0-7,k0-7)(m8-15,k0-7)(m0-7,k8-15)(m8-15,k8-15)
    const uint32_t a_r  = (uint32_t)((lane & 7) + ((lane >> 3) & 1) * 8);
    const uint32_t a_cb = (uint32_t)(((lane >> 4) & 1) * 16);
    // B x4 blocks in reg order: (n0-7,k0-7)(n0-7,k8-15)(n8-15,k0-7)(n8-15,k8-15)
    const uint32_t b_r  = (uint32_t)((lane & 7) + ((lane >> 4) & 1) * 8);
    const uint32_t b_cb = (uint32_t)(((lane >> 3) & 1) * 16);

    for (int t = 0; t < T; t++) {
        if (t + 3 <= T) { CP_WAIT(2); }
        else if (t + 2 == T) { CP_WAIT(1); }
        else { CP_WAIT(0); }
        __syncthreads();
        const uint32_t sb = su + (t % NSTAGES) * STAGE;

#pragma unroll
        for (int kk = 0; kk < BK / 16; kk++) {
            const uint32_t kb = (uint32_t)(kk * 32);
            uint32_t a[4][4];
#pragma unroll
            for (int ms = 0; ms < 4; ms++)
                ldsm_x4(a[ms], sb + A_OFF
                               + (uint32_t)(mw + ms * 16 + a_r) * ROWB + kb + a_cb);
            uint32_t b[4][4];
#pragma unroll
            for (int ns = 0; ns < 4; ns++)
                ldsm_x4(b[ns], sb + B_OFF
                               + (uint32_t)(nw + ns * 16 + b_r) * ROWB + kb + b_cb);
#pragma unroll
            for (int ms = 0; ms < 4; ms++)
#pragma unroll
                for (int n8 = 0; n8 < 8; n8++)
                    mma_fp16(acc[ms][n8], a[ms], &b[n8 >> 1][(n8 & 1) * 2]);
        }

        __syncthreads();
        if (t + 3 < T) load_stage(t % NSTAGES, t + 3);
    }

    // epilogue: fused bias, float2 stores
#pragma unroll
    for (int n8 = 0; n8 < 8; n8++) {
        const int n0 = bn + nw + n8 * 8 + 2 * (lane & 3);
        const float bv0 = BIAS[n0];
        const float bv1 = BIAS[n0 + 1];
#pragma unroll
        for (int ms = 0; ms < 4; ms++) {
            const int m0 = bm + mw + ms * 16 + (lane >> 2);
            float2 v;
            v.x = acc[ms][n8][0] + bv0;
            v.y = acc[ms][n8][1] + bv1;
            *reinterpret_cast<float2*>(Y + (size_t)m0 * N + n0) = v;
            v.x = acc[ms][n8][2] + bv0;
            v.y = acc[ms][n8][3] + bv1;
            *reinterpret_cast<float2*>(Y + (size_t)(m0 + 8) * N + n0) = v;
        }
    }
}

}  // namespace

extern "C" void kernel_launch(void* const* d_in, const int* in_sizes, int n_in,
                              void* d_out, int out_size) {
    const float* x    = (const float*)d_in[0];
    const int*   qw   = (const int*)d_in[1];
    const float* sc   = (const float*)d_in[2];
    const float* zp   = (const float*)d_in[3];
    const float* bias = (const float*)d_in[4];
    float* y = (float*)d_out;

    const int N = in_sizes[4];
    const long long K = ((long long)in_sizes[1] * 8) / N;
    const long long M = (long long)in_sizes[0] / K;

    cudaFuncSetAttribute(gemm_kernel, cudaFuncAttributeMaxDynamicSharedMemorySize,
                         SMEM_TOTAL);

    {   // x -> fp16
        long total4 = (long)M * K / 4;
        int blocks = (int)((total4 + 255) / 256);
        convert_x_kernel<<<blocks, 256>>>(x, total4);
    }
    {   // dequant W -> fp16
        int wordsPerRow = (int)(K / 8);
        int nGroups = (int)(K / 128);
        long totalWords = (long)N * wordsPerRow;
        int blocks = (int)((totalWords + 255) / 256);
        convert_w_kernel<<<blocks, 256>>>(qw, sc, zp, wordsPerRow, nGroups, totalWords);
    }
    {
        dim3 grid((unsigned)(N / BN), (unsigned)(M / BM));
        gemm_kernel<<<grid, THREADS, SMEM_TOTAL>>>(bias, y, (int)M, N, (int)K);
    }
}

// round 5
// speedup vs baseline: 7.2683x; 1.0166x over previous
#include <cuda_runtime.h>
#include <cuda_fp16.h>
#include <cstdint>

// Fused int4 group-dequant + GEMM via single-product fp16 mma.sync.
// Round 5: 4-stage cp.async pipeline, ONE __syncthreads per k-tile, loads
// issued before compute (uniform in-flight depth via empty commit groups).

namespace {

constexpr int MMAX = 8192, NMAX = 4096, KMAX = 4096;

__device__ __half g_X[(size_t)MMAX * KMAX];
__device__ __half g_W[(size_t)NMAX * KMAX];

constexpr int BM = 128, BN = 256, BK = 64;
constexpr int THREADS = 256;
constexpr int ROWB = 144;                 // 64 fp16 = 128B + 16B pad
constexpr int A_OFF = 0;
constexpr int B_OFF = BM * ROWB;          // 18432
constexpr int STAGE = B_OFF + BN * ROWB;  // 55296
constexpr int NSTAGES = 4;
constexpr int SMEM_TOTAL = NSTAGES * STAGE;  // 221184

__device__ __forceinline__ uint32_t smem_u32(const void* p) {
    uint32_t a;
    asm("{ .reg .u64 t; cvta.to.shared.u64 t, %1; cvt.u32.u64 %0, t; }"
        : "=r"(a) : "l"(p));
    return a;
}
__device__ __forceinline__ void cp16(uint32_t dst, const void* src) {
    asm volatile("cp.async.cg.shared.global [%0], [%1], 16;"
                 :: "r"(dst), "l"(src) : "memory");
}
#define CP_COMMIT() asm volatile("cp.async.commit_group;" ::: "memory")
#define CP_WAIT(n)  asm volatile("cp.async.wait_group %0;" :: "n"(n) : "memory")

__device__ __forceinline__ void ldsm_x4(uint32_t* r, uint32_t addr) {
    asm volatile("ldmatrix.sync.aligned.m8n8.x4.shared.b16 {%0,%1,%2,%3}, [%4];"
                 : "=r"(r[0]), "=r"(r[1]), "=r"(r[2]), "=r"(r[3]) : "r"(addr));
}
__device__ __forceinline__ void mma_fp16(float* c, const uint32_t* a,
                                         const uint32_t* b) {
    asm volatile(
        "mma.sync.aligned.m16n8k16.row.col.f32.f16.f16.f32 "
        "{%0,%1,%2,%3}, {%4,%5,%6,%7}, {%8,%9}, {%0,%1,%2,%3};"
        : "+f"(c[0]), "+f"(c[1]), "+f"(c[2]), "+f"(c[3])
        : "r"(a[0]), "r"(a[1]), "r"(a[2]), "r"(a[3]), "r"(b[0]), "r"(b[1]));
}

// ---- pre-pass: x -> fp16 ----
__global__ __launch_bounds__(256)
void convert_x_kernel(const float* __restrict__ X, long total4) {
    long i = (long)blockIdx.x * blockDim.x + threadIdx.x;
    if (i >= total4) return;
    float4 v = reinterpret_cast<const float4*>(X)[i];
    __half2* H = reinterpret_cast<__half2*>(g_X);
    H[2 * i]     = __floats2half2_rn(v.x, v.y);
    H[2 * i + 1] = __floats2half2_rn(v.z, v.w);
}

// ---- pre-pass: dequant W (int4, group scale/zp) -> fp16 ----
__global__ __launch_bounds__(256)
void convert_w_kernel(const int* __restrict__ QW, const float* __restrict__ SC,
                      const float* __restrict__ ZP, int wordsPerRow, int nGroups,
                      long totalWords) {
    long i = (long)blockIdx.x * blockDim.x + threadIdx.x;
    if (i >= totalWords) return;
    int n = (int)(i / wordsPerRow);
    int w = (int)(i % wordsPerRow);
    int g = (w * 8) >> 7;  // group_size 128 = 16 int32 words
    float s = SC[(size_t)n * nGroups + g];
    float z = ZP[(size_t)n * nGroups + g];
    float szn = -s * z;
    unsigned q = (unsigned)QW[i];
    __half2 h[4];
#pragma unroll
    for (int j = 0; j < 4; j++) {
        float f0 = fmaf(s, (float)((q >> (8 * j)) & 0xFu), szn);
        float f1 = fmaf(s, (float)((q >> (8 * j + 4)) & 0xFu), szn);
        h[j] = __floats2half2_rn(f0, f1);
    }
    reinterpret_cast<uint2*>(g_W)[2 * i]     = *reinterpret_cast<uint2*>(&h[0]);
    reinterpret_cast<uint2*>(g_W)[2 * i + 1] = *reinterpret_cast<uint2*>(&h[2]);
}

// ---- main GEMM: 128x256 CTA, BK=64, 8 warps (2x4), warp tile 64x64 ----
__global__ __launch_bounds__(THREADS, 1)
void gemm_kernel(const float* __restrict__ BIAS, float* __restrict__ Y,
                 int M, int N, int K) {
    extern __shared__ char smem[];
    const uint32_t su = smem_u32(smem);
    const int tid  = threadIdx.x;
    const int lane = tid & 31;
    const int wid  = tid >> 5;
    const int bm = blockIdx.y * BM;
    const int bn = blockIdx.x * BN;
    const int mw = (wid >> 2) * 64;   // 2 warps along m
    const int nw = (wid & 3) * 64;    // 4 warps along n

    auto load_stage = [&](int s, int t) {
        const uint32_t sb = su + s * STAGE;
        const size_t k0 = (size_t)t * BK;
#pragma unroll
        for (int j = 0; j < 4; j++) {  // A: 128 rows x 8 x 16B
            int idx = tid + j * THREADS;
            int r = idx >> 3, c = idx & 7;
            cp16(sb + A_OFF + (uint32_t)(r * ROWB + c * 16),
                 (const char*)(g_X + (size_t)(bm + r) * K + k0) + c * 16);
        }
#pragma unroll
        for (int j = 0; j < 8; j++) {  // B: 256 rows x 8 x 16B
            int idx = tid + j * THREADS;
            int r = idx >> 3, c = idx & 7;
            cp16(sb + B_OFF + (uint32_t)(r * ROWB + c * 16),
                 (const char*)(g_W + (size_t)(bn + r) * K + k0) + c * 16);
        }
        CP_COMMIT();
    };

    float acc[4][8][4];
#pragma unroll
    for (int i = 0; i < 4; i++)
#pragma unroll
        for (int j = 0; j < 8; j++)
#pragma unroll
            for (int c = 0; c < 4; c++) acc[i][j][c] = 0.f;

    const int T = K / BK;  // 64
    load_stage(0, 0);
    load_stage(1, 1);
    load_stage(2, 2);

    // ldmatrix lane addressing
    const uint32_t a_r  = (uint32_t)((lane & 7) + ((lane >> 3) & 1) * 8);
    const uint32_t a_cb = (uint32_t)(((lane >> 4) & 1) * 16);
    const uint32_t b_r  = (uint32_t)((lane & 7) + ((lane >> 4) & 1) * 8);
    const uint32_t b_cb = (uint32_t)(((lane >> 3) & 1) * 16);

    for (int t = 0; t < T; t++) {
        // In-flight groups at this point: {t, t+1, t+2} (some possibly empty
        // at the tail). Waiting for <=2 completes group t.
        CP_WAIT(2);
        __syncthreads();

        // Issue next load BEFORE compute. Writes stage (t+3)%4 == (t-1)%4,
        // whose readers all passed the barrier above. Empty commit at tail
        // keeps the in-flight count uniform.
        if (t + 3 < T) load_stage((t + 3) & 3, t + 3);
        else           CP_COMMIT();

        const uint32_t sb = su + (t & 3) * STAGE;

#pragma unroll
        for (int kk = 0; kk < BK / 16; kk++) {
            const uint32_t kb = (uint32_t)(kk * 32);
            uint32_t a[4][4];
#pragma unroll
            for (int ms = 0; ms < 4; ms++)
                ldsm_x4(a[ms], sb + A_OFF
                               + (uint32_t)(mw + ms * 16 + a_r) * ROWB + kb + a_cb);
            uint32_t b[4][4];
#pragma unroll
            for (int ns = 0; ns < 4; ns++)
                ldsm_x4(b[ns], sb + B_OFF
                               + (uint32_t)(nw + ns * 16 + b_r) * ROWB + kb + b_cb);
#pragma unroll
            for (int ms = 0; ms < 4; ms++)
#pragma unroll
                for (int n8 = 0; n8 < 8; n8++)
                    mma_fp16(acc[ms][n8], a[ms], &b[n8 >> 1][(n8 & 1) * 2]);
        }
    }

    // epilogue: fused bias, float2 stores
#pragma unroll
    for (int n8 = 0; n8 < 8; n8++) {
        const int n0 = bn + nw + n8 * 8 + 2 * (lane & 3);
        const float bv0 = BIAS[n0];
        const float bv1 = BIAS[n0 + 1];
#pragma unroll
        for (int ms = 0; ms < 4; ms++) {
            const int m0 = bm + mw + ms * 16 + (lane >> 2);
            float2 v;
            v.x = acc[ms][n8][0] + bv0;
            v.y = acc[ms][n8][1] + bv1;
            *reinterpret_cast<float2*>(Y + (size_t)m0 * N + n0) = v;
            v.x = acc[ms][n8][2] + bv0;
            v.y = acc[ms][n8][3] + bv1;
            *reinterpret_cast<float2*>(Y + (size_t)(m0 + 8) * N + n0) = v;
        }
    }
}

}  // namespace

extern "C" void kernel_launch(void* const* d_in, const int* in_sizes, int n_in,
                              void* d_out, int out_size) {
    const float* x    = (const float*)d_in[0];
    const int*   qw   = (const int*)d_in[1];
    const float* sc   = (const float*)d_in[2];
    const float* zp   = (const float*)d_in[3];
    const float* bias = (const float*)d_in[4];
    float* y = (float*)d_out;

    const int N = in_sizes[4];
    const long long K = ((long long)in_sizes[1] * 8) / N;
    const long long M = (long long)in_sizes[0] / K;

    cudaFuncSetAttribute(gemm_kernel, cudaFuncAttributeMaxDynamicSharedMemorySize,
                         SMEM_TOTAL);

    {   // x -> fp16
        long total4 = (long)M * K / 4;
        int blocks = (int)((total4 + 255) / 256);
        convert_x_kernel<<<blocks, 256>>>(x, total4);
    }
    {   // dequant W -> fp16
        int wordsPerRow = (int)(K / 8);
        int nGroups = (int)(K / 128);
        long totalWords = (long)N * wordsPerRow;
        int blocks = (int)((totalWords + 255) / 256);
        convert_w_kernel<<<blocks, 256>>>(qw, sc, zp, wordsPerRow, nGroups, totalWords);
    }
    {
        dim3 grid((unsigned)(N / BN), (unsigned)(M / BM));
        gemm_kernel<<<grid, THREADS, SMEM_TOTAL>>>(bias, y, (int)M, N, (int)K);
    }
}

// round 6
// speedup vs baseline: 7.5631x; 1.0406x over previous
#include <cuda_runtime.h>
#include <cuda_fp16.h>
#include <cstdint>

// Fused int4 group-dequant + GEMM via single-product fp16 mma.sync.
// Round 6: same 128x256x64 tile + 4-stage single-barrier cp.async pipeline,
// but 512 threads (16 warps, warp tile 64x32) -> 4 warps/SMSP to hide the
// ldmatrix->mma latency chain that bound round 5 (2 warps/SMSP, ~13cyc/HMMA).

namespace {

constexpr int MMAX = 8192, NMAX = 4096, KMAX = 4096;

__device__ __half g_X[(size_t)MMAX * KMAX];
__device__ __half g_W[(size_t)NMAX * KMAX];

constexpr int BM = 128, BN = 256, BK = 64;
constexpr int THREADS = 512;
constexpr int ROWB = 144;                 // 64 fp16 = 128B + 16B pad
constexpr int A_OFF = 0;
constexpr int B_OFF = BM * ROWB;          // 18432
constexpr int STAGE = B_OFF + BN * ROWB;  // 55296
constexpr int NSTAGES = 4;
constexpr int SMEM_TOTAL = NSTAGES * STAGE;  // 221184

__device__ __forceinline__ uint32_t smem_u32(const void* p) {
    uint32_t a;
    asm("{ .reg .u64 t; cvta.to.shared.u64 t, %1; cvt.u32.u64 %0, t; }"
        : "=r"(a) : "l"(p));
    return a;
}
__device__ __forceinline__ void cp16(uint32_t dst, const void* src) {
    asm volatile("cp.async.cg.shared.global [%0], [%1], 16;"
                 :: "r"(dst), "l"(src) : "memory");
}
#define CP_COMMIT() asm volatile("cp.async.commit_group;" ::: "memory")
#define CP_WAIT(n)  asm volatile("cp.async.wait_group %0;" :: "n"(n) : "memory")

__device__ __forceinline__ void ldsm_x4(uint32_t* r, uint32_t addr) {
    asm volatile("ldmatrix.sync.aligned.m8n8.x4.shared.b16 {%0,%1,%2,%3}, [%4];"
                 : "=r"(r[0]), "=r"(r[1]), "=r"(r[2]), "=r"(r[3]) : "r"(addr));
}
__device__ __forceinline__ void mma_fp16(float* c, const uint32_t* a,
                                         const uint32_t* b) {
    asm volatile(
        "mma.sync.aligned.m16n8k16.row.col.f32.f16.f16.f32 "
        "{%0,%1,%2,%3}, {%4,%5,%6,%7}, {%8,%9}, {%0,%1,%2,%3};"
        : "+f"(c[0]), "+f"(c[1]), "+f"(c[2]), "+f"(c[3])
        : "r"(a[0]), "r"(a[1]), "r"(a[2]), "r"(a[3]), "r"(b[0]), "r"(b[1]));
}

// ---- pre-pass: x -> fp16 ----
__global__ __launch_bounds__(256)
void convert_x_kernel(const float* __restrict__ X, long total4) {
    long i = (long)blockIdx.x * blockDim.x + threadIdx.x;
    if (i >= total4) return;
    float4 v = reinterpret_cast<const float4*>(X)[i];
    __half2* H = reinterpret_cast<__half2*>(g_X);
    H[2 * i]     = __floats2half2_rn(v.x, v.y);
    H[2 * i + 1] = __floats2half2_rn(v.z, v.w);
}

// ---- pre-pass: dequant W (int4, group scale/zp) -> fp16 ----
__global__ __launch_bounds__(256)
void convert_w_kernel(const int* __restrict__ QW, const float* __restrict__ SC,
                      const float* __restrict__ ZP, int wordsPerRow, int nGroups,
                      long totalWords) {
    long i = (long)blockIdx.x * blockDim.x + threadIdx.x;
    if (i >= totalWords) return;
    int n = (int)(i / wordsPerRow);
    int w = (int)(i % wordsPerRow);
    int g = (w * 8) >> 7;  // group_size 128 = 16 int32 words
    float s = SC[(size_t)n * nGroups + g];
    float z = ZP[(size_t)n * nGroups + g];
    float szn = -s * z;
    unsigned q = (unsigned)QW[i];
    __half2 h[4];
#pragma unroll
    for (int j = 0; j < 4; j++) {
        float f0 = fmaf(s, (float)((q >> (8 * j)) & 0xFu), szn);
        float f1 = fmaf(s, (float)((q >> (8 * j + 4)) & 0xFu), szn);
        h[j] = __floats2half2_rn(f0, f1);
    }
    reinterpret_cast<uint2*>(g_W)[2 * i]     = *reinterpret_cast<uint2*>(&h[0]);
    reinterpret_cast<uint2*>(g_W)[2 * i + 1] = *reinterpret_cast<uint2*>(&h[2]);
}

// ---- main GEMM: 128x256 CTA, BK=64, 16 warps (2x8), warp tile 64x32 ----
__global__ __launch_bounds__(THREADS, 1)
void gemm_kernel(const float* __restrict__ BIAS, float* __restrict__ Y,
                 int M, int N, int K) {
    extern __shared__ char smem[];
    const uint32_t su = smem_u32(smem);
    const int tid  = threadIdx.x;
    const int lane = tid & 31;
    const int wid  = tid >> 5;
    const int bm = blockIdx.y * BM;
    const int bn = blockIdx.x * BN;
    const int mw = (wid >> 3) * 64;   // 2 warps along m
    const int nw = (wid & 7) * 32;    // 8 warps along n

    auto load_stage = [&](int s, int t) {
        const uint32_t sb = su + s * STAGE;
        const size_t k0 = (size_t)t * BK;
#pragma unroll
        for (int j = 0; j < 2; j++) {  // A: 128 rows x 8 x 16B = 1024 chunks
            int idx = tid + j * THREADS;
            int r = idx >> 3, c = idx & 7;
            cp16(sb + A_OFF + (uint32_t)(r * ROWB + c * 16),
                 (const char*)(g_X + (size_t)(bm + r) * K + k0) + c * 16);
        }
#pragma unroll
        for (int j = 0; j < 4; j++) {  // B: 256 rows x 8 x 16B = 2048 chunks
            int idx = tid + j * THREADS;
            int r = idx >> 3, c = idx & 7;
            cp16(sb + B_OFF + (uint32_t)(r * ROWB + c * 16),
                 (const char*)(g_W + (size_t)(bn + r) * K + k0) + c * 16);
        }
        CP_COMMIT();
    };

    float acc[4][4][4];
#pragma unroll
    for (int i = 0; i < 4; i++)
#pragma unroll
        for (int j = 0; j < 4; j++)
#pragma unroll
            for (int c = 0; c < 4; c++) acc[i][j][c] = 0.f;

    const int T = K / BK;  // 64
    load_stage(0, 0);
    load_stage(1, 1);
    load_stage(2, 2);

    // ldmatrix lane addressing
    const uint32_t a_r  = (uint32_t)((lane & 7) + ((lane >> 3) & 1) * 8);
    const uint32_t a_cb = (uint32_t)(((lane >> 4) & 1) * 16);
    const uint32_t b_r  = (uint32_t)((lane & 7) + ((lane >> 4) & 1) * 8);
    const uint32_t b_cb = (uint32_t)(((lane >> 3) & 1) * 16);

    for (int t = 0; t < T; t++) {
        // In-flight groups: {t, t+1, t+2}; wait <=2 completes group t.
        CP_WAIT(2);
        __syncthreads();

        // Issue next load BEFORE compute: writes stage (t+3)%4 == (t-1)%4,
        // already consumed by all warps (barrier above). Empty commits at
        // the tail keep in-flight depth uniform.
        if (t + 3 < T) load_stage((t + 3) & 3, t + 3);
        else           CP_COMMIT();

        const uint32_t sb = su + (t & 3) * STAGE;

#pragma unroll
        for (int kk = 0; kk < BK / 16; kk++) {
            const uint32_t kb = (uint32_t)(kk * 32);
            uint32_t a[4][4];
#pragma unroll
            for (int ms = 0; ms < 4; ms++)
                ldsm_x4(a[ms], sb + A_OFF
                               + (uint32_t)(mw + ms * 16 + a_r) * ROWB + kb + a_cb);
            uint32_t b[2][4];
#pragma unroll
            for (int ns = 0; ns < 2; ns++)
                ldsm_x4(b[ns], sb + B_OFF
                               + (uint32_t)(nw + ns * 16 + b_r) * ROWB + kb + b_cb);
#pragma unroll
            for (int ms = 0; ms < 4; ms++)
#pragma unroll
                for (int n8 = 0; n8 < 4; n8++)
                    mma_fp16(acc[ms][n8], a[ms], &b[n8 >> 1][(n8 & 1) * 2]);
        }
    }

    // epilogue: fused bias, float2 stores
#pragma unroll
    for (int n8 = 0; n8 < 4; n8++) {
        const int n0 = bn + nw + n8 * 8 + 2 * (lane & 3);
        const float bv0 = BIAS[n0];
        const float bv1 = BIAS[n0 + 1];
#pragma unroll
        for (int ms = 0; ms < 4; ms++) {
            const int m0 = bm + mw + ms * 16 + (lane >> 2);
            float2 v;
            v.x = acc[ms][n8][0] + bv0;
            v.y = acc[ms][n8][1] + bv1;
            *reinterpret_cast<float2*>(Y + (size_t)m0 * N + n0) = v;
            v.x = acc[ms][n8][2] + bv0;
            v.y = acc[ms][n8][3] + bv1;
            *reinterpret_cast<float2*>(Y + (size_t)(m0 + 8) * N + n0) = v;
        }
    }
}

}  // namespace

extern "C" void kernel_launch(void* const* d_in, const int* in_sizes, int n_in,
                              void* d_out, int out_size) {
    const float* x    = (const float*)d_in[0];
    const int*   qw   = (const int*)d_in[1];
    const float* sc   = (const float*)d_in[2];
    const float* zp   = (const float*)d_in[3];
    const float* bias = (const float*)d_in[4];
    float* y = (float*)d_out;

    const int N = in_sizes[4];
    const long long K = ((long long)in_sizes[1] * 8) / N;
    const long long M = (long long)in_sizes[0] / K;

    cudaFuncSetAttribute(gemm_kernel, cudaFuncAttributeMaxDynamicSharedMemorySize,
                         SMEM_TOTAL);

    {   // x -> fp16
        long total4 = (long)M * K / 4;
        int blocks = (int)((total4 + 255) / 256);
        convert_x_kernel<<<blocks, 256>>>(x, total4);
    }
    {   // dequant W -> fp16
        int wordsPerRow = (int)(K / 8);
        int nGroups = (int)(K / 128);
        long totalWords = (long)N * wordsPerRow;
        int blocks = (int)((totalWords + 255) / 256);
        convert_w_kernel<<<blocks, 256>>>(qw, sc, zp, wordsPerRow, nGroups, totalWords);
    }
    {
        dim3 grid((unsigned)(N / BN), (unsigned)(M / BM));
        gemm_kernel<<<grid, THREADS, SMEM_TOTAL>>>(bias, y, (int)M, N, (int)K);
    }
}

// round 7
// speedup vs baseline: 7.7831x; 1.0291x over previous
#include <cuda_runtime.h>
#include <cuda_fp16.h>
#include <cstdint>

// Fused int4 group-dequant + GEMM via single-product fp16 mma.sync.
// Round 7: 128x128 CTA tile, 256 threads, 3-stage pipeline, 2 CTAs per SM.
// Two independent barrier domains per SM keep the HMMA pipe fed while one
// CTA sits in its tile-boundary sync/wait/ldsm ramp (the measured ~37% gap).

namespace {

constexpr int MMAX = 8192, NMAX = 4096, KMAX = 4096;

__device__ __half g_X[(size_t)MMAX * KMAX];
__device__ __half g_W[(size_t)NMAX * KMAX];

constexpr int BM = 128, BN = 128, BK = 64;
constexpr int THREADS = 256;
constexpr int ROWB = 144;                 // 64 fp16 = 128B + 16B pad
constexpr int A_OFF = 0;
constexpr int B_OFF = BM * ROWB;          // 18432
constexpr int STAGE = B_OFF + BN * ROWB;  // 36864
constexpr int NSTAGES = 3;
constexpr int SMEM_TOTAL = NSTAGES * STAGE;  // 110592 -> 2 CTAs/SM = 221184

__device__ __forceinline__ uint32_t smem_u32(const void* p) {
    uint32_t a;
    asm("{ .reg .u64 t; cvta.to.shared.u64 t, %1; cvt.u32.u64 %0, t; }"
        : "=r"(a) : "l"(p));
    return a;
}
__device__ __forceinline__ void cp16(uint32_t dst, const void* src) {
    asm volatile("cp.async.cg.shared.global [%0], [%1], 16;"
                 :: "r"(dst), "l"(src) : "memory");
}
#define CP_COMMIT() asm volatile("cp.async.commit_group;" ::: "memory")
#define CP_WAIT(n)  asm volatile("cp.async.wait_group %0;" :: "n"(n) : "memory")

__device__ __forceinline__ void ldsm_x4(uint32_t* r, uint32_t addr) {
    asm volatile("ldmatrix.sync.aligned.m8n8.x4.shared.b16 {%0,%1,%2,%3}, [%4];"
                 : "=r"(r[0]), "=r"(r[1]), "=r"(r[2]), "=r"(r[3]) : "r"(addr));
}
__device__ __forceinline__ void mma_fp16(float* c, const uint32_t* a,
                                         const uint32_t* b) {
    asm volatile(
        "mma.sync.aligned.m16n8k16.row.col.f32.f16.f16.f32 "
        "{%0,%1,%2,%3}, {%4,%5,%6,%7}, {%8,%9}, {%0,%1,%2,%3};"
        : "+f"(c[0]), "+f"(c[1]), "+f"(c[2]), "+f"(c[3])
        : "r"(a[0]), "r"(a[1]), "r"(a[2]), "r"(a[3]), "r"(b[0]), "r"(b[1]));
}

// ---- pre-pass: x -> fp16 ----
__global__ __launch_bounds__(256)
void convert_x_kernel(const float* __restrict__ X, long total4) {
    long i = (long)blockIdx.x * blockDim.x + threadIdx.x;
    if (i >= total4) return;
    float4 v = reinterpret_cast<const float4*>(X)[i];
    __half2* H = reinterpret_cast<__half2*>(g_X);
    H[2 * i]     = __floats2half2_rn(v.x, v.y);
    H[2 * i + 1] = __floats2half2_rn(v.z, v.w);
}

// ---- pre-pass: dequant W (int4, group scale/zp) -> fp16 ----
__global__ __launch_bounds__(256)
void convert_w_kernel(const int* __restrict__ QW, const float* __restrict__ SC,
                      const float* __restrict__ ZP, int wordsPerRow, int nGroups,
                      long totalWords) {
    long i = (long)blockIdx.x * blockDim.x + threadIdx.x;
    if (i >= totalWords) return;
    int n = (int)(i / wordsPerRow);
    int w = (int)(i % wordsPerRow);
    int g = (w * 8) >> 7;  // group_size 128 = 16 int32 words
    float s = SC[(size_t)n * nGroups + g];
    float z = ZP[(size_t)n * nGroups + g];
    float szn = -s * z;
    unsigned q = (unsigned)QW[i];
    __half2 h[4];
#pragma unroll
    for (int j = 0; j < 4; j++) {
        float f0 = fmaf(s, (float)((q >> (8 * j)) & 0xFu), szn);
        float f1 = fmaf(s, (float)((q >> (8 * j + 4)) & 0xFu), szn);
        h[j] = __floats2half2_rn(f0, f1);
    }
    reinterpret_cast<uint2*>(g_W)[2 * i]     = *reinterpret_cast<uint2*>(&h[0]);
    reinterpret_cast<uint2*>(g_W)[2 * i + 1] = *reinterpret_cast<uint2*>(&h[2]);
}

// ---- main GEMM: 128x128 CTA, BK=64, 8 warps (2x4), warp tile 64x32 ----
__global__ __launch_bounds__(THREADS, 2)
void gemm_kernel(const float* __restrict__ BIAS, float* __restrict__ Y,
                 int M, int N, int K) {
    extern __shared__ char smem[];
    const uint32_t su = smem_u32(smem);
    const int tid  = threadIdx.x;
    const int lane = tid & 31;
    const int wid  = tid >> 5;
    const int bm = blockIdx.y * BM;
    const int bn = blockIdx.x * BN;
    const int mw = (wid >> 2) * 64;   // 2 warps along m
    const int nw = (wid & 3) * 32;    // 4 warps along n

    auto load_stage = [&](int s, int t) {
        const uint32_t sb = su + s * STAGE;
        const size_t k0 = (size_t)t * BK;
#pragma unroll
        for (int j = 0; j < 4; j++) {  // A: 128 rows x 8 x 16B = 1024 chunks
            int idx = tid + j * THREADS;
            int r = idx >> 3, c = idx & 7;
            cp16(sb + A_OFF + (uint32_t)(r * ROWB + c * 16),
                 (const char*)(g_X + (size_t)(bm + r) * K + k0) + c * 16);
        }
#pragma unroll
        for (int j = 0; j < 4; j++) {  // B: 128 rows x 8 x 16B = 1024 chunks
            int idx = tid + j * THREADS;
            int r = idx >> 3, c = idx & 7;
            cp16(sb + B_OFF + (uint32_t)(r * ROWB + c * 16),
                 (const char*)(g_W + (size_t)(bn + r) * K + k0) + c * 16);
        }
        CP_COMMIT();
    };

    float acc[4][4][4];
#pragma unroll
    for (int i = 0; i < 4; i++)
#pragma unroll
        for (int j = 0; j < 4; j++)
#pragma unroll
            for (int c = 0; c < 4; c++) acc[i][j][c] = 0.f;

    const int T = K / BK;  // 64
    load_stage(0, 0);
    load_stage(1, 1);

    // ldmatrix lane addressing
    const uint32_t a_r  = (uint32_t)((lane & 7) + ((lane >> 3) & 1) * 8);
    const uint32_t a_cb = (uint32_t)(((lane >> 4) & 1) * 16);
    const uint32_t b_r  = (uint32_t)((lane & 7) + ((lane >> 4) & 1) * 8);
    const uint32_t b_cb = (uint32_t)(((lane >> 3) & 1) * 16);

    for (int t = 0; t < T; t++) {
        // In-flight groups: {t, t+1}; wait <=1 completes group t.
        CP_WAIT(1);
        __syncthreads();

        // Issue load(t+2) into stage (t+2)%3 == (t-1)%3, whose readers all
        // passed the barrier above. Empty commits keep depth uniform.
        if (t + 2 < T) load_stage((t + 2) % 3, t + 2);
        else           CP_COMMIT();

        const uint32_t sb = su + (t % 3) * STAGE;

#pragma unroll
        for (int kk = 0; kk < BK / 16; kk++) {
            const uint32_t kb = (uint32_t)(kk * 32);
            uint32_t a[4][4];
#pragma unroll
            for (int ms = 0; ms < 4; ms++)
                ldsm_x4(a[ms], sb + A_OFF
                               + (uint32_t)(mw + ms * 16 + a_r) * ROWB + kb + a_cb);
            uint32_t b[2][4];
#pragma unroll
            for (int ns = 0; ns < 2; ns++)
                ldsm_x4(b[ns], sb + B_OFF
                               + (uint32_t)(nw + ns * 16 + b_r) * ROWB + kb + b_cb);
#pragma unroll
            for (int ms = 0; ms < 4; ms++)
#pragma unroll
                for (int n8 = 0; n8 < 4; n8++)
                    mma_fp16(acc[ms][n8], a[ms], &b[n8 >> 1][(n8 & 1) * 2]);
        }
    }

    // epilogue: fused bias, float2 stores
#pragma unroll
    for (int n8 = 0; n8 < 4; n8++) {
        const int n0 = bn + nw + n8 * 8 + 2 * (lane & 3);
        const float bv0 = BIAS[n0];
        const float bv1 = BIAS[n0 + 1];
#pragma unroll
        for (int ms = 0; ms < 4; ms++) {
            const int m0 = bm + mw + ms * 16 + (lane >> 2);
            float2 v;
            v.x = acc[ms][n8][0] + bv0;
            v.y = acc[ms][n8][1] + bv1;
            *reinterpret_cast<float2*>(Y + (size_t)m0 * N + n0) = v;
            v.x = acc[ms][n8][2] + bv0;
            v.y = acc[ms][n8][3] + bv1;
            *reinterpret_cast<float2*>(Y + (size_t)(m0 + 8) * N + n0) = v;
        }
    }
}

}  // namespace

extern "C" void kernel_launch(void* const* d_in, const int* in_sizes, int n_in,
                              void* d_out, int out_size) {
    const float* x    = (const float*)d_in[0];
    const int*   qw   = (const int*)d_in[1];
    const float* sc   = (const float*)d_in[2];
    const float* zp   = (const float*)d_in[3];
    const float* bias = (const float*)d_in[4];
    float* y = (float*)d_out;

    const int N = in_sizes[4];
    const long long K = ((long long)in_sizes[1] * 8) / N;
    const long long M = (long long)in_sizes[0] / K;

    cudaFuncSetAttribute(gemm_kernel, cudaFuncAttributeMaxDynamicSharedMemorySize,
                         SMEM_TOTAL);

    {   // x -> fp16
        long total4 = (long)M * K / 4;
        int blocks = (int)((total4 + 255) / 256);
        convert_x_kernel<<<blocks, 256>>>(x, total4);
    }
    {   // dequant W -> fp16
        int wordsPerRow = (int)(K / 8);
        int nGroups = (int)(K / 128);
        long totalWords = (long)N * wordsPerRow;
        int blocks = (int)((totalWords + 255) / 256);
        convert_w_kernel<<<blocks, 256>>>(qw, sc, zp, wordsPerRow, nGroups, totalWords);
    }
    {
        dim3 grid((unsigned)(N / BN), (unsigned)(M / BM));
        gemm_kernel<<<grid, THREADS, SMEM_TOTAL>>>(bias, y, (int)M, N, (int)K);
    }
}